// round 11
// baseline (speedup 1.0000x reference)
#include <cuda_runtime.h>
#include <math.h>

#define NT 64
#define NH 2048
#define NI 1408
#define NE 32
#define NK 4
#define NPAIR (NT * NK)
#define MAXSLOT (NPAIR + NE * 3)   // per-expert padding to multiple of 4

// ---- scratch (device globals: no allocation allowed) ----
__device__ int   d_expert_count[NE];
__device__ int   d_expert_start[NE];     // multiple-of-4 starts
__device__ int   d_pair_token[MAXSLOT];  // slot -> token (pads -> 0)
__device__ int   d_pair_idx[NT * NK];    // (token,k) -> slot
__device__ float d_topk_w[NT * NK];      // routing weights
__device__ float d_mixed[MAXSLOT * NI];  // silu(g)*u per slot
__device__ float d_pair_out[MAXSLOT * NH];

// ---- packed f32x2 helpers (FFMA2: PTX-only on sm_103a) ----
__device__ __forceinline__ unsigned long long fma2(unsigned long long a,
                                                   unsigned long long b,
                                                   unsigned long long c) {
    unsigned long long d;
    asm("fma.rn.f32x2 %0, %1, %2, %3;" : "=l"(d) : "l"(a), "l"(b), "l"(c));
    return d;
}
__device__ __forceinline__ unsigned long long add2(unsigned long long a,
                                                   unsigned long long b) {
    unsigned long long d;
    asm("add.rn.f32x2 %0, %1, %2;" : "=l"(d) : "l"(a), "l"(b));
    return d;
}
__device__ __forceinline__ float fold2(unsigned long long v) {
    float lo, hi;
    asm("mov.b64 {%0, %1}, %2;" : "=f"(lo), "=f"(hi) : "l"(v));
    return lo + hi;
}
// warp-reduce a packed f32x2 accumulator, then fold halves
__device__ __forceinline__ float wred(unsigned long long v) {
#pragma unroll
    for (int o = 16; o > 0; o >>= 1)
        v = add2(v, __shfl_down_sync(0xFFFFFFFFu, v, o));
    return fold2(v);
}

// ============================================================
// Kernel 1: routing. One block, one thread per token.
// ============================================================
__global__ void route_kernel(const float* __restrict__ logits) {
    __shared__ int s_count[NE];
    __shared__ int s_start[NE];
    __shared__ int s_slot[NE];
    const int t = threadIdx.x;

    if (t < NE) { s_count[t] = 0; s_slot[t] = 0; }
    __syncthreads();

    float v[NE];
#pragma unroll
    for (int e = 0; e < NE; e++) v[e] = logits[t * NE + e];

    int ids[NK];
    float vals[NK];
#pragma unroll
    for (int k = 0; k < NK; k++) {
        int best = 0;
        float bv = -1e30f;
#pragma unroll
        for (int e = 0; e < NE; e++) {
            if (v[e] > bv) { bv = v[e]; best = e; }  // strict > : lowest index wins ties
        }
        ids[k] = best;
        vals[k] = bv;
        v[best] = -1e30f;
    }

    float m = vals[0];
    float w[NK];
    float s = 0.f;
#pragma unroll
    for (int k = 0; k < NK; k++) { w[k] = expf(vals[k] - m); s += w[k]; }
    float inv = 1.f / s;
#pragma unroll
    for (int k = 0; k < NK; k++) d_topk_w[t * NK + k] = w[k] * inv;

#pragma unroll
    for (int k = 0; k < NK; k++) atomicAdd(&s_count[ids[k]], 1);
    __syncthreads();

    if (t == 0) {
        int off = 0;
        for (int e = 0; e < NE; e++) {
            s_start[e] = off;
            off += (s_count[e] + 3) & ~3;   // pad each expert region to mult of 4
        }
    }
    __syncthreads();

#pragma unroll
    for (int k = 0; k < NK; k++) {
        int slot = atomicAdd(&s_slot[ids[k]], 1);
        int p = s_start[ids[k]] + slot;
        d_pair_token[p] = t;
        d_pair_idx[t * NK + k] = p;
    }
    if (t < NE) {
        d_expert_count[t] = s_count[t];
        d_expert_start[t] = s_start[t];
        const int cnt = s_count[t];
        const int padded = (cnt + 3) & ~3;
        for (int p = cnt; p < padded; p++)      // pad slots -> token 0
            d_pair_token[s_start[t] + p] = 0;
    }
}

// ============================================================
// Kernel 2: gate/up matvecs + SiLU.
// Block = 256 thr (8 warps), covers 16 inter rows.
// Per 4-token chunk: stage x rows into SMEM (32KB, read from L2
// ONCE per block), then each warp streams 2 gate + 2 up rows.
// FFMA2 halves = (k, k+1): all loads dense, zero movs.
// ============================================================
__global__ void __launch_bounds__(256) gateup_kernel(
    const float* __restrict__ x,
    const float* __restrict__ w_gate, const float* __restrict__ w_up)
{
    __shared__ float sx[4 * NH];   // 32 KB: 4 token rows

    const int e = blockIdx.y;
    const int nT = d_expert_count[e];
    if (nT == 0) return;
    const int start = d_expert_start[e];     // multiple of 4
    const int tid = threadIdx.x;
    const int warp = tid >> 5;
    const int lane = tid & 31;
    const int i0 = blockIdx.x * 16 + warp * 2;   // 2 inter rows per warp

    const ulonglong2* __restrict__ G0 = (const ulonglong2*)(w_gate + ((size_t)e * NI + i0) * NH);
    const ulonglong2* __restrict__ G1 = (const ulonglong2*)(w_gate + ((size_t)e * NI + i0 + 1) * NH);
    const ulonglong2* __restrict__ U0 = (const ulonglong2*)(w_up   + ((size_t)e * NI + i0) * NH);
    const ulonglong2* __restrict__ U1 = (const ulonglong2*)(w_up   + ((size_t)e * NI + i0 + 1) * NH);

    constexpr int ITERS = NH / 4 / 32;   // 16

    for (int c = 0; c < nT; c += 4) {
        // ---- stage 4 token rows into SMEM ----
        __syncthreads();   // protect previous chunk's sx
#pragma unroll
        for (int q = 0; q < 4 * NH / 4 / 256; q++) {   // 8 float4 per thread
            const int idx = tid + q * 256;             // [0, 2048)
            const int tr = idx >> 9;                   // token 0..3
            const int kk = idx & 511;                  // float4 index in row
            const int tok = d_pair_token[start + c + tr];
            ((float4*)sx)[idx] = __ldg((const float4*)(x + (size_t)tok * NH) + kk);
        }
        __syncthreads();

        // ---- mainloop: 4 weight streams x 4 tokens ----
        unsigned long long ag0[4], ag1[4], au0[4], au1[4];
#pragma unroll
        for (int t = 0; t < 4; t++) { ag0[t] = 0ull; ag1[t] = 0ull; au0[t] = 0ull; au1[t] = 0ull; }

#pragma unroll
        for (int it = 0; it < ITERS; it++) {
            const int kq = lane + 32 * it;
            const ulonglong2 wg0 = __ldg(&G0[kq]);
            const ulonglong2 wg1 = __ldg(&G1[kq]);
            const ulonglong2 wu0 = __ldg(&U0[kq]);
            const ulonglong2 wu1 = __ldg(&U1[kq]);
#pragma unroll
            for (int t = 0; t < 4; t++) {
                const ulonglong2 xv = *(const ulonglong2*)&sx[t * NH + kq * 4];
                ag0[t] = fma2(wg0.x, xv.x, ag0[t]); ag0[t] = fma2(wg0.y, xv.y, ag0[t]);
                ag1[t] = fma2(wg1.x, xv.x, ag1[t]); ag1[t] = fma2(wg1.y, xv.y, ag1[t]);
                au0[t] = fma2(wu0.x, xv.x, au0[t]); au0[t] = fma2(wu0.y, xv.y, au0[t]);
                au1[t] = fma2(wu1.x, xv.x, au1[t]); au1[t] = fma2(wu1.y, xv.y, au1[t]);
            }
        }

        // ---- reduce + SiLU + write ----
#pragma unroll
        for (int t = 0; t < 4; t++) {
            const float g0 = wred(ag0[t]);
            const float g1 = wred(ag1[t]);
            const float u0 = wred(au0[t]);
            const float u1 = wred(au1[t]);
            if (lane == 0) {
                float* mo = d_mixed + (size_t)(start + c + t) * NI + i0;
                mo[0] = (g0 / (1.f + expf(-g0))) * u0;
                mo[1] = (g1 / (1.f + expf(-g1))) * u1;
            }
        }
    }
}

// ============================================================
// Kernel 3: down projection.
// Block = 256 thr (8 warps), covers 32 hidden rows.
// Per 4-token chunk: stage mixed rows (22KB SMEM, contiguous
// slots -> one flat copy), each warp streams 4 weight rows.
// ============================================================
__global__ void __launch_bounds__(256) down_kernel(const float* __restrict__ w_down)
{
    __shared__ float sm[4 * NI];   // 22.5 KB

    const int e = blockIdx.y;
    const int nT = d_expert_count[e];
    if (nT == 0) return;
    const int start = d_expert_start[e];
    const int tid = threadIdx.x;
    const int warp = tid >> 5;
    const int lane = tid & 31;
    const int h0 = blockIdx.x * 32 + warp * 4;   // 4 hidden rows per warp

    const ulonglong2* __restrict__ R0 = (const ulonglong2*)(w_down + ((size_t)e * NH + h0) * NI);
    const ulonglong2* __restrict__ R1 = (const ulonglong2*)(w_down + ((size_t)e * NH + h0 + 1) * NI);
    const ulonglong2* __restrict__ R2 = (const ulonglong2*)(w_down + ((size_t)e * NH + h0 + 2) * NI);
    const ulonglong2* __restrict__ R3 = (const ulonglong2*)(w_down + ((size_t)e * NH + h0 + 3) * NI);

    constexpr int ITERS = NI / 4 / 32;   // 11

    for (int c = 0; c < nT; c += 4) {
        // ---- stage 4 mixed rows (contiguous slots) ----
        __syncthreads();
        {
            const float4* __restrict__ src = (const float4*)(d_mixed + (size_t)(start + c) * NI);
#pragma unroll
            for (int q = 0; q < 4 * NI / 4 / 256 + 1; q++) {
                const int idx = tid + q * 256;
                if (idx < 4 * NI / 4) ((float4*)sm)[idx] = __ldg(&src[idx]);
            }
        }
        __syncthreads();

        unsigned long long a0[4], a1[4], a2[4], a3[4];
#pragma unroll
        for (int t = 0; t < 4; t++) { a0[t] = 0ull; a1[t] = 0ull; a2[t] = 0ull; a3[t] = 0ull; }

#pragma unroll
        for (int it = 0; it < ITERS; it++) {
            const int kq = lane + 32 * it;
            const ulonglong2 w0 = __ldg(&R0[kq]);
            const ulonglong2 w1 = __ldg(&R1[kq]);
            const ulonglong2 w2 = __ldg(&R2[kq]);
            const ulonglong2 w3 = __ldg(&R3[kq]);
#pragma unroll
            for (int t = 0; t < 4; t++) {
                const ulonglong2 xv = *(const ulonglong2*)&sm[t * NI + kq * 4];
                a0[t] = fma2(w0.x, xv.x, a0[t]); a0[t] = fma2(w0.y, xv.y, a0[t]);
                a1[t] = fma2(w1.x, xv.x, a1[t]); a1[t] = fma2(w1.y, xv.y, a1[t]);
                a2[t] = fma2(w2.x, xv.x, a2[t]); a2[t] = fma2(w2.y, xv.y, a2[t]);
                a3[t] = fma2(w3.x, xv.x, a3[t]); a3[t] = fma2(w3.y, xv.y, a3[t]);
            }
        }

#pragma unroll
        for (int t = 0; t < 4; t++) {
            const float v0 = wred(a0[t]);
            const float v1 = wred(a1[t]);
            const float v2 = wred(a2[t]);
            const float v3 = wred(a3[t]);
            if (lane == 0) {
                float* po = d_pair_out + (size_t)(start + c + t) * NH + h0;
                po[0] = v0; po[1] = v1; po[2] = v2; po[3] = v3;
            }
        }
    }
}

// ============================================================
// Kernel 4: weighted combine of the 4 routed pair outputs.
// ============================================================
__global__ void combine_kernel(float* __restrict__ out)
{
    const int idx = blockIdx.x * blockDim.x + threadIdx.x;  // [0, NT*NH)
    const int t = idx / NH;
    const int h = idx - t * NH;
    float s = 0.f;
#pragma unroll
    for (int k = 0; k < NK; k++) {
        const int p = d_pair_idx[t * NK + k];
        s = fmaf(d_topk_w[t * NK + k], d_pair_out[(size_t)p * NH + h], s);
    }
    out[idx] = s;
}

// ============================================================
extern "C" void kernel_launch(void* const* d_in, const int* in_sizes, int n_in,
                              void* d_out, int out_size)
{
    const float* x      = (const float*)d_in[0];
    const float* logits = (const float*)d_in[1];
    const float* wg     = (const float*)d_in[2];
    const float* wu     = (const float*)d_in[3];
    const float* wd     = (const float*)d_in[4];
    float* out = (float*)d_out;

    route_kernel<<<1, NT>>>(logits);
    gateup_kernel<<<dim3(NI / 16, NE), 256>>>(x, wg, wu);
    down_kernel<<<dim3(NH / 32, NE), 256>>>(wd);
    combine_kernel<<<(NT * NH) / 256, 256>>>(out);
}